// round 6
// baseline (speedup 1.0000x reference)
#include <cuda_runtime.h>
#include <cuda_bf16.h>

#define NB 128
#define NT 512
#define EMBED 1024
#define WIN 64
#define NK (2*WIN+1)   // 129
#define GW 256         // matrix W dimension

// Scratch (device globals: no allocation allowed)
__device__ float g_q[EMBED];
__device__ float g_wpart[4][EMBED];
__device__ float g_s[NK];
__device__ float g_abar[EMBED];
__device__ float g_o[EMBED];
// Grid barrier state: monotonic counters -> safe across graph replays, no reset.
// Arrival: one atomicAdd on a single counter per block (cheap).
// Release: per-block flags 128B apart -> each block polls its OWN L2 line
// (no same-address atomic serialization; B300 doc: 63x faster than shared addr).
__device__ unsigned g_arrive = 0;
__device__ unsigned g_flag[NB * 32];   // flag i at g_flag[i*32], 128 B stride

__device__ __forceinline__ void grid_sync() {
    __shared__ unsigned s_go;
    __threadfence();            // publish this thread's stores before arriving
    __syncthreads();            // all threads in block done
    unsigned target = 0;
    if (threadIdx.x == 0) {
        unsigned a = atomicAdd(&g_arrive, 1u) + 1u;
        target = (a + NB - 1u) / NB;            // episode this block waits for
        s_go = ((a % NB) == 0u) ? target : 0u;  // last arriver -> broadcast release
    }
    __syncthreads();
    unsigned rel = s_go;
    if (rel != 0u) {
        // Last-arriving block: 128 threads release all flags in one wave.
        if (threadIdx.x < NB) atomicExch(&g_flag[threadIdx.x * 32], rel);
    } else if (threadIdx.x == 0) {
        // Poll own flag: single poller per address, atomic read + backoff.
        while (atomicAdd(&g_flag[blockIdx.x * 32], 0u) < target) { __nanosleep(32); }
        __threadfence();
    }
    __syncthreads();
}

__device__ __forceinline__ float warp_reduce(float v) {
    #pragma unroll
    for (int o = 16; o; o >>= 1) v += __shfl_xor_sync(0xffffffffu, v, o);
    return v;
}

__device__ __forceinline__ float dot4(float4 a, float4 b) {
    return a.x * b.x + a.y * b.y + a.z * b.z + a.w * b.w;
}

// Shared memory regions (floats)
//  R0 [0,1024)      : x / q / w staging (256 float4)
//  R1 [1024,3072)   : big reduction buffer (512 float4 or 512 floats)
//  R2 [3072,3328)   : second-stage reduction (64 float4)
//  R3 [3328,3457)   : s_sh
//  R4 [3472,3601)   : p_sh
//  R5 [3616,3712)   : misc (warp accs, zinv)
#define SM_TOTAL 3712

__global__ void __launch_bounds__(NT, 1)
fused_local_attn(const float* __restrict__ matrix,
                 const float* __restrict__ Wq, const float* __restrict__ bq,
                 const float* __restrict__ Wk,
                 const float* __restrict__ Wv, const float* __restrict__ bv,
                 const float* __restrict__ Wo, const float* __restrict__ bo,
                 const int* __restrict__ ppx, const int* __restrict__ ppy,
                 float* __restrict__ out)
{
    const int tid  = threadIdx.x;
    const int bid  = blockIdx.x;
    const int wid  = tid >> 5;
    const int lane = tid & 31;

    __shared__ __align__(16) float sm[SM_TOTAL];
    float4* R0_4 = (float4*)sm;                 // 256 float4
    float4* R1_4 = (float4*)(sm + 1024);        // 512 float4
    float4* R2_4 = (float4*)(sm + 3072);        // 64 float4
    float*  R1   = sm + 1024;
    float*  s_sh = sm + 3328;
    float*  p_sh = sm + 3472;
    float*  misc = sm + 3616;

    const int px = ppx[0], py = ppy[0];
    const int hq = 2 * px - WIN;
    const int wq = 2 * py - WIN;
    const float* rowbase = matrix + (size_t)hq * GW * EMBED;
    const float4* xvec4 = (const float4*)(rowbase + (size_t)wq * EMBED);
    const float*  keys  = rowbase + (size_t)(py - WIN) * EMBED;
    const float4* keys4 = (const float4*)keys;

    // =========== Phase A: q = Wq @ x + bq (8 rows/block, 2 warps/row) ====
    {
        if (tid < 256) R0_4[tid] = xvec4[tid];
        __syncthreads();
        int row = bid * 8 + (wid >> 1);
        int half = wid & 1;
        const float4* Wrow = (const float4*)(Wq + (size_t)row * EMBED);
        float4 w0 = Wrow[half * 128 + 0 * 32 + lane];
        float4 w1 = Wrow[half * 128 + 1 * 32 + lane];
        float4 w2 = Wrow[half * 128 + 2 * 32 + lane];
        float4 w3 = Wrow[half * 128 + 3 * 32 + lane];
        float acc = dot4(w0, R0_4[half * 128 + 0 * 32 + lane])
                  + dot4(w1, R0_4[half * 128 + 1 * 32 + lane])
                  + dot4(w2, R0_4[half * 128 + 2 * 32 + lane])
                  + dot4(w3, R0_4[half * 128 + 3 * 32 + lane]);
        acc = warp_reduce(acc);
        if (lane == 0) misc[wid] = acc;
        __syncthreads();
        if (tid < 8) g_q[bid * 8 + tid] = misc[2 * tid] + misc[2 * tid + 1] + bq[bid * 8 + tid];
    }
    grid_sync();

    // =========== Phase B: w-partials.  block = (fc, et): fc=bid>>5 (4 f-chunks
    // of 256), et=bid&31 (32 e's).  w[e] = sum_f q[f]*Wk[f][e]. ===========
    {
        int fc = bid >> 5, et = bid & 31;
        int f0 = fc * 256;
        if (tid < 64) R0_4[tid] = __ldcg(&((const float4*)g_q)[f0 / 4 + tid]);
        __syncthreads();
        const float* sq = sm;
        int v = tid & 7;                         // float4 column within 32-e tile
        float4 acc = make_float4(0.f, 0.f, 0.f, 0.f);
        #pragma unroll
        for (int i = 0; i < 4; i++) {
            int fl = i * 64 + (tid >> 3);
            float qf = sq[fl];
            float4 wv = ((const float4*)Wk)[(size_t)(f0 + fl) * 256 + et * 8 + v];
            acc.x += qf * wv.x; acc.y += qf * wv.y; acc.z += qf * wv.z; acc.w += qf * wv.w;
        }
        R1_4[tid] = acc;
        __syncthreads();
        if (tid < 64) {                           // stage 1: 512 -> 64
            int vv = tid & 7, g = tid >> 3;
            float4 s = make_float4(0.f, 0.f, 0.f, 0.f);
            #pragma unroll
            for (int j = 0; j < 8; j++) {
                float4 t4 = R1_4[vv + 8 * (g * 8 + j)];
                s.x += t4.x; s.y += t4.y; s.z += t4.z; s.w += t4.w;
            }
            R2_4[tid] = s;
        }
        __syncthreads();
        if (tid < 8) {                            // stage 2: 64 -> 8 float4
            float4 s = make_float4(0.f, 0.f, 0.f, 0.f);
            #pragma unroll
            for (int g = 0; g < 8; g++) {
                float4 t4 = R2_4[tid + 8 * g];
                s.x += t4.x; s.y += t4.y; s.z += t4.z; s.w += t4.w;
            }
            ((float4*)g_wpart[fc])[et * 8 + tid] = s;
        }
    }
    grid_sync();

    // ===== Phase C: reduce w-partials (prologue) + s[k] = w . a_k ========
    {
        if (tid < 256) {                          // w into R0 (4 coalesced L2 reads)
            float4 s = __ldcg(&((const float4*)g_wpart[0])[tid]);
            #pragma unroll
            for (int fc = 1; fc < 4; fc++) {
                float4 t4 = __ldcg(&((const float4*)g_wpart[fc])[tid]);
                s.x += t4.x; s.y += t4.y; s.z += t4.z; s.w += t4.w;
            }
            R0_4[tid] = s;
        }
        __syncthreads();
        for (int k = bid; k < NK; k += NB) {      // block 0 also does k=128
            float p = 0.f;
            if (tid < 256) p = dot4(R0_4[tid], keys4[k * 256 + tid]);
            p = warp_reduce(p);
            if (lane == 0 && wid < 8) misc[wid] = p;
            __syncthreads();
            if (tid == 0) {
                float s = 0.f;
                #pragma unroll
                for (int j = 0; j < 8; j++) s += misc[j];
                g_s[k] = s;
            }
            __syncthreads();
        }
    }
    grid_sync();

    // ===== Phase D: softmax + abar[e] = sum_k p[k]*a_k[e] (8 e's/block) ==
    {
        if (tid < NK) s_sh[tid] = __ldcg(&g_s[tid]);
        __syncthreads();
        const float scale = 0.03125f;             // 1/sqrt(1024)
        if (wid == 0) {
            float m = -1e30f;
            for (int k = lane; k < NK; k += 32) m = fmaxf(m, s_sh[k]);
            #pragma unroll
            for (int o = 16; o; o >>= 1) m = fmaxf(m, __shfl_xor_sync(0xffffffffu, m, o));
            float z = 0.f;
            for (int k = lane; k < NK; k += 32) {
                float e = __expf((s_sh[k] - m) * scale);
                p_sh[k] = e;
                z += e;
            }
            z = warp_reduce(z);
            if (lane == 0) misc[16] = 1.f / z;
        }
        __syncthreads();
        float zinv = misc[16];
        int eidx = tid & 7, kpart = tid >> 3;     // 64 k-partitions
        int e = bid * 8 + eidx;
        float acc = 0.f;
        for (int k = kpart; k < NK; k += 64)
            acc += p_sh[k] * __ldcg(&keys[(size_t)k * EMBED + e]);
        R1[tid] = acc;
        __syncthreads();
        if (tid < 64) {                           // 512 -> 64
            int vv = tid & 7, g = tid >> 3;
            float s = 0.f;
            #pragma unroll
            for (int j = 0; j < 8; j++) s += R1[vv + 8 * (g * 8 + j)];
            sm[3072 + tid] = s;                   // reuse R2 as scalar
        }
        __syncthreads();
        if (tid < 8) {                            // 64 -> 8
            float s = 0.f;
            #pragma unroll
            for (int g = 0; g < 8; g++) s += sm[3072 + tid + 8 * g];
            g_abar[bid * 8 + tid] = s * zinv;
        }
    }
    grid_sync();

    // =========== Phase E: o = Wv @ abar + bv =============================
    {
        if (tid < 256) R0_4[tid] = __ldcg(&((const float4*)g_abar)[tid]);
        __syncthreads();
        int row = bid * 8 + (wid >> 1);
        int half = wid & 1;
        const float4* Wrow = (const float4*)(Wv + (size_t)row * EMBED);
        float4 w0 = Wrow[half * 128 + 0 * 32 + lane];
        float4 w1 = Wrow[half * 128 + 1 * 32 + lane];
        float4 w2 = Wrow[half * 128 + 2 * 32 + lane];
        float4 w3 = Wrow[half * 128 + 3 * 32 + lane];
        float acc = dot4(w0, R0_4[half * 128 + 0 * 32 + lane])
                  + dot4(w1, R0_4[half * 128 + 1 * 32 + lane])
                  + dot4(w2, R0_4[half * 128 + 2 * 32 + lane])
                  + dot4(w3, R0_4[half * 128 + 3 * 32 + lane]);
        acc = warp_reduce(acc);
        if (lane == 0) misc[wid] = acc;
        __syncthreads();
        if (tid < 8) g_o[bid * 8 + tid] = misc[2 * tid] + misc[2 * tid + 1] + bv[bid * 8 + tid];
    }
    grid_sync();

    // =========== Phase F: out = Wo @ o + bo ==============================
    {
        if (tid < 256) R0_4[tid] = __ldcg(&((const float4*)g_o)[tid]);
        __syncthreads();
        int row = bid * 8 + (wid >> 1);
        int half = wid & 1;
        const float4* Wrow = (const float4*)(Wo + (size_t)row * EMBED);
        float4 w0 = Wrow[half * 128 + 0 * 32 + lane];
        float4 w1 = Wrow[half * 128 + 1 * 32 + lane];
        float4 w2 = Wrow[half * 128 + 2 * 32 + lane];
        float4 w3 = Wrow[half * 128 + 3 * 32 + lane];
        float acc = dot4(w0, R0_4[half * 128 + 0 * 32 + lane])
                  + dot4(w1, R0_4[half * 128 + 1 * 32 + lane])
                  + dot4(w2, R0_4[half * 128 + 2 * 32 + lane])
                  + dot4(w3, R0_4[half * 128 + 3 * 32 + lane]);
        acc = warp_reduce(acc);
        if (lane == 0) misc[wid] = acc;
        __syncthreads();
        if (tid < 8) out[bid * 8 + tid] = misc[2 * tid] + misc[2 * tid + 1] + bo[bid * 8 + tid];
    }
}

extern "C" void kernel_launch(void* const* d_in, const int* in_sizes, int n_in,
                              void* d_out, int out_size) {
    const float* matrix = (const float*)d_in[0];
    const float* Wq = (const float*)d_in[1];
    const float* bq = (const float*)d_in[2];
    const float* Wk = (const float*)d_in[3];
    // d_in[4] = bk: mathematically eliminated (constant shift under softmax)
    const float* Wv = (const float*)d_in[5];
    const float* bv = (const float*)d_in[6];
    const float* Wo = (const float*)d_in[7];
    const float* bo = (const float*)d_in[8];
    const int* px = (const int*)d_in[9];
    const int* py = (const int*)d_in[10];

    fused_local_attn<<<NB, NT>>>(matrix, Wq, bq, Wk, Wv, bv, Wo, bo, px, py,
                                 (float*)d_out);
}

// round 7
// speedup vs baseline: 1.0472x; 1.0472x over previous
#include <cuda_runtime.h>
#include <cuda_bf16.h>

#define NB 128
#define NT 512
#define EMBED 1024
#define WIN 64
#define NK (2*WIN+1)   // 129
#define GW 256         // matrix W dimension

// Scratch (device globals: no allocation allowed)
__device__ float g_q[EMBED];
__device__ float g_wpart[4][EMBED];
__device__ float g_s[NK];
__device__ float g_abar[EMBED];
__device__ float g_o[EMBED];
// Grid barrier state: EXACT R5 implementation (best passing config).
__device__ unsigned g_arrive = 0;
__device__ unsigned g_rel = 0;

__device__ __forceinline__ void grid_sync() {
    __threadfence();
    __syncthreads();
    if (threadIdx.x == 0) {
        unsigned a = atomicAdd(&g_arrive, 1u) + 1u;
        unsigned target = (a + NB - 1u) / NB;
        if ((a % NB) == 0u) {
            atomicAdd(&g_rel, 1u);
        } else {
            while (atomicAdd(&g_rel, 0u) < target) { __nanosleep(32); }
        }
    }
    __syncthreads();
}

__device__ __forceinline__ float warp_reduce(float v) {
    #pragma unroll
    for (int o = 16; o; o >>= 1) v += __shfl_xor_sync(0xffffffffu, v, o);
    return v;
}

__device__ __forceinline__ float dot4(float4 a, float4 b) {
    return a.x * b.x + a.y * b.y + a.z * b.z + a.w * b.w;
}

__device__ __forceinline__ void cp_async16(unsigned smem_addr, const void* gptr) {
    asm volatile("cp.async.cg.shared.global [%0], [%1], 16;"
                 :: "r"(smem_addr), "l"(gptr));
}

// Dynamic smem layout (floats):
//  R0    [0,1024)        x / q / w / abar / o staging (256 float4)
//  R1    [1024,3072)     big reduction buffer
//  R2    [3072,3328)     second-stage reduction
//  s_sh  [3328,3457)
//  p_sh  [3472,3601)
//  misc  [3616,3712)
//  keyC  [3712,5760)     this block's key (block 0: two keys)
//  keyD  [5760,6800)     129 x 8 key columns for phase D
//  WvS   [6800,14992)    8 Wv rows (32KB)
//  WoS   [14992,23184)   8 Wo rows (32KB)
#define SM_FLOATS 23184
#define SM_BYTES  (SM_FLOATS * 4)

__global__ void __launch_bounds__(NT, 1)
fused_local_attn(const float* __restrict__ matrix,
                 const float* __restrict__ Wq, const float* __restrict__ bq,
                 const float* __restrict__ Wk,
                 const float* __restrict__ Wv, const float* __restrict__ bv,
                 const float* __restrict__ Wo, const float* __restrict__ bo,
                 const int* __restrict__ ppx, const int* __restrict__ ppy,
                 float* __restrict__ out)
{
    const int tid  = threadIdx.x;
    const int bid  = blockIdx.x;
    const int wid  = tid >> 5;
    const int lane = tid & 31;

    extern __shared__ __align__(16) float sm[];
    float4* R0_4   = (float4*)sm;
    float4* R1_4   = (float4*)(sm + 1024);
    float4* R2_4   = (float4*)(sm + 3072);
    float*  R1     = sm + 1024;
    float*  s_sh   = sm + 3328;
    float*  p_sh   = sm + 3472;
    float*  misc   = sm + 3616;
    float*  keyC   = sm + 3712;
    float4* keyC_4 = (float4*)keyC;
    float*  kd     = sm + 5760;
    float4* kd_4   = (float4*)kd;
    float*  WvS    = sm + 6800;
    float4* WvS_4  = (float4*)WvS;
    float*  WoS    = sm + 14992;
    float4* WoS_4  = (float4*)WoS;

    const int row  = bid * 8 + (wid >> 1);   // GEMV row this warp-pair owns
    const int half = wid & 1;

    // ---- Prefetch 1: weight registers (independent of px/py) ------------
    const float4* Wq4 = (const float4*)(Wq + (size_t)row * EMBED);
    float4 qa0 = Wq4[half * 128 + 0 * 32 + lane];
    float4 qa1 = Wq4[half * 128 + 1 * 32 + lane];
    float4 qa2 = Wq4[half * 128 + 2 * 32 + lane];
    float4 qa3 = Wq4[half * 128 + 3 * 32 + lane];

    const int fc = bid >> 5, et = bid & 31;  // phase-B tile coords
    const int f0 = fc * 256;
    const int v  = tid & 7;
    float4 kb0 = ((const float4*)Wk)[(size_t)(f0 + 0 * 64 + (tid >> 3)) * 256 + et * 8 + v];
    float4 kb1 = ((const float4*)Wk)[(size_t)(f0 + 1 * 64 + (tid >> 3)) * 256 + et * 8 + v];
    float4 kb2 = ((const float4*)Wk)[(size_t)(f0 + 2 * 64 + (tid >> 3)) * 256 + et * 8 + v];
    float4 kb3 = ((const float4*)Wk)[(size_t)(f0 + 3 * 64 + (tid >> 3)) * 256 + et * 8 + v];

    // ---- Prefetch 2: Wv, Wo -> smem via cp.async (no register cost) -----
    {
        unsigned wv_s = (unsigned)__cvta_generic_to_shared(WvS_4);
        unsigned wo_s = (unsigned)__cvta_generic_to_shared(WoS_4);
        const float4* vsrc = (const float4*)Wv + (size_t)bid * 2048;
        const float4* osrc = (const float4*)Wo + (size_t)bid * 2048;
        #pragma unroll
        for (int j = 0; j < 4; j++)
            cp_async16(wv_s + (unsigned)(tid + j * 512) * 16u, vsrc + tid + j * 512);
        asm volatile("cp.async.commit_group;");
        #pragma unroll
        for (int j = 0; j < 4; j++)
            cp_async16(wo_s + (unsigned)(tid + j * 512) * 16u, osrc + tid + j * 512);
        asm volatile("cp.async.commit_group;");
    }

    // ---- Prefetch 3: px/py-dependent data ------------------------------
    const int px = ppx[0], py = ppy[0];
    const int hq = 2 * px - WIN;
    const int wq = 2 * py - WIN;
    const float* rowbase = matrix + (size_t)hq * GW * EMBED;
    const float4* xvec4 = (const float4*)(rowbase + (size_t)wq * EMBED);
    const float*  keys  = rowbase + (size_t)(py - WIN) * EMBED;
    const float4* keys4 = (const float4*)keys;

    if (tid < 256) R0_4[tid] = xvec4[tid];                 // x stage
    if (tid >= 256) keyC_4[tid - 256] = keys4[(size_t)bid * 256 + (tid - 256)];
    if (bid == 0 && tid >= 256)                            // block 0: also k=128
        keyC_4[256 + (tid - 256)] = keys4[(size_t)128 * 256 + (tid - 256)];
    if (tid < 258)                                          // keyD columns (one 32B sector per k)
        kd_4[tid] = keys4[(size_t)(tid >> 1) * 256 + bid * 2 + (tid & 1)];
    __syncthreads();

    // =========== Phase A: q = Wq @ x + bq ================================
    {
        float acc = dot4(qa0, R0_4[half * 128 + 0 * 32 + lane])
                  + dot4(qa1, R0_4[half * 128 + 1 * 32 + lane])
                  + dot4(qa2, R0_4[half * 128 + 2 * 32 + lane])
                  + dot4(qa3, R0_4[half * 128 + 3 * 32 + lane]);
        acc = warp_reduce(acc);
        if (lane == 0) misc[wid] = acc;
        __syncthreads();
        if (tid < 8) g_q[bid * 8 + tid] = misc[2 * tid] + misc[2 * tid + 1] + bq[bid * 8 + tid];
    }
    grid_sync();

    // =========== Phase B: w-partials (Wk already in registers) ===========
    {
        if (tid < 64) R0_4[tid] = __ldcg(&((const float4*)g_q)[f0 / 4 + tid]);
        __syncthreads();
        const float* sq = sm;
        float4 acc = make_float4(0.f, 0.f, 0.f, 0.f);
        float q0 = sq[0 * 64 + (tid >> 3)];
        float q1 = sq[1 * 64 + (tid >> 3)];
        float q2 = sq[2 * 64 + (tid >> 3)];
        float q3 = sq[3 * 64 + (tid >> 3)];
        acc.x = q0 * kb0.x + q1 * kb1.x + q2 * kb2.x + q3 * kb3.x;
        acc.y = q0 * kb0.y + q1 * kb1.y + q2 * kb2.y + q3 * kb3.y;
        acc.z = q0 * kb0.z + q1 * kb1.z + q2 * kb2.z + q3 * kb3.z;
        acc.w = q0 * kb0.w + q1 * kb1.w + q2 * kb2.w + q3 * kb3.w;
        R1_4[tid] = acc;
        __syncthreads();
        if (tid < 64) {                           // stage 1: 512 -> 64
            int vv = tid & 7, g = tid >> 3;
            float4 s = make_float4(0.f, 0.f, 0.f, 0.f);
            #pragma unroll
            for (int j = 0; j < 8; j++) {
                float4 t4 = R1_4[vv + 8 * (g * 8 + j)];
                s.x += t4.x; s.y += t4.y; s.z += t4.z; s.w += t4.w;
            }
            R2_4[tid] = s;
        }
        __syncthreads();
        if (tid < 8) {                            // stage 2: 64 -> 8 float4
            float4 s = make_float4(0.f, 0.f, 0.f, 0.f);
            #pragma unroll
            for (int g = 0; g < 8; g++) {
                float4 t4 = R2_4[tid + 8 * g];
                s.x += t4.x; s.y += t4.y; s.z += t4.z; s.w += t4.w;
            }
            ((float4*)g_wpart[fc])[et * 8 + tid] = s;
        }
    }
    grid_sync();

    // ===== Phase C: reduce w-partials + s[k] = w . key_sm ===============
    {
        if (tid < 256) {
            float4 s = __ldcg(&((const float4*)g_wpart[0])[tid]);
            #pragma unroll
            for (int f = 1; f < 4; f++) {
                float4 t4 = __ldcg(&((const float4*)g_wpart[f])[tid]);
                s.x += t4.x; s.y += t4.y; s.z += t4.z; s.w += t4.w;
            }
            R0_4[tid] = s;
        }
        __syncthreads();
        int it = 0;
        for (int k = bid; k < NK; k += NB, ++it) {
            float p = 0.f;
            if (tid < 256) p = dot4(R0_4[tid], keyC_4[it * 256 + tid]);
            p = warp_reduce(p);
            if (lane == 0 && wid < 8) misc[wid] = p;
            __syncthreads();
            if (tid == 0) {
                float s = 0.f;
                #pragma unroll
                for (int j = 0; j < 8; j++) s += misc[j];
                g_s[k] = s;
            }
            __syncthreads();
        }
    }
    grid_sync();

    // ===== Phase D: softmax + abar from smem key columns =================
    {
        if (tid < NK) s_sh[tid] = __ldcg(&g_s[tid]);
        __syncthreads();
        const float scale = 0.03125f;             // 1/sqrt(1024)
        if (wid == 0) {
            float m = -1e30f;
            for (int k = lane; k < NK; k += 32) m = fmaxf(m, s_sh[k]);
            #pragma unroll
            for (int o = 16; o; o >>= 1) m = fmaxf(m, __shfl_xor_sync(0xffffffffu, m, o));
            float z = 0.f;
            for (int k = lane; k < NK; k += 32) {
                float e = __expf((s_sh[k] - m) * scale);
                p_sh[k] = e;
                z += e;
            }
            z = warp_reduce(z);
            if (lane == 0) misc[16] = 1.f / z;
        }
        __syncthreads();
        float zinv = misc[16];
        int eidx = tid & 7, kpart = tid >> 3;     // 64 k-partitions
        float acc = 0.f;
        for (int k = kpart; k < NK; k += 64)
            acc += p_sh[k] * kd[k * 8 + eidx];
        R1[tid] = acc;
        __syncthreads();
        if (tid < 64) {                           // 512 -> 64
            int vv = tid & 7, g = tid >> 3;
            float s = 0.f;
            #pragma unroll
            for (int j = 0; j < 8; j++) s += R1[vv + 8 * (g * 8 + j)];
            sm[3072 + tid] = s;
        }
        __syncthreads();
        if (tid < 8) {                            // 64 -> 8
            float s = 0.f;
            #pragma unroll
            for (int g = 0; g < 8; g++) s += sm[3072 + tid + 8 * g];
            g_abar[bid * 8 + tid] = s * zinv;
        }
    }
    grid_sync();

    // =========== Phase E: o = Wv @ abar + bv (Wv in smem) ================
    asm volatile("cp.async.wait_group 1;");
    __syncthreads();
    {
        if (tid < 256) R0_4[tid] = __ldcg(&((const float4*)g_abar)[tid]);
        __syncthreads();
        int r = wid >> 1;
        float acc = dot4(WvS_4[r * 256 + half * 128 + 0 * 32 + lane], R0_4[half * 128 + 0 * 32 + lane])
                  + dot4(WvS_4[r * 256 + half * 128 + 1 * 32 + lane], R0_4[half * 128 + 1 * 32 + lane])
                  + dot4(WvS_4[r * 256 + half * 128 + 2 * 32 + lane], R0_4[half * 128 + 2 * 32 + lane])
                  + dot4(WvS_4[r * 256 + half * 128 + 3 * 32 + lane], R0_4[half * 128 + 3 * 32 + lane]);
        acc = warp_reduce(acc);
        if (lane == 0) misc[wid] = acc;
        __syncthreads();
        if (tid < 8) g_o[bid * 8 + tid] = misc[2 * tid] + misc[2 * tid + 1] + bv[bid * 8 + tid];
    }
    grid_sync();

    // =========== Phase F: out = Wo @ o + bo (Wo in smem) =================
    asm volatile("cp.async.wait_group 0;");
    __syncthreads();
    {
        if (tid < 256) R0_4[tid] = __ldcg(&((const float4*)g_o)[tid]);
        __syncthreads();
        int r = wid >> 1;
        float acc = dot4(WoS_4[r * 256 + half * 128 + 0 * 32 + lane], R0_4[half * 128 + 0 * 32 + lane])
                  + dot4(WoS_4[r * 256 + half * 128 + 1 * 32 + lane], R0_4[half * 128 + 1 * 32 + lane])
                  + dot4(WoS_4[r * 256 + half * 128 + 2 * 32 + lane], R0_4[half * 128 + 2 * 32 + lane])
                  + dot4(WoS_4[r * 256 + half * 128 + 3 * 32 + lane], R0_4[half * 128 + 3 * 32 + lane]);
        acc = warp_reduce(acc);
        if (lane == 0) misc[wid] = acc;
        __syncthreads();
        if (tid < 8) out[bid * 8 + tid] = misc[2 * tid] + misc[2 * tid + 1] + bo[bid * 8 + tid];
    }
}

extern "C" void kernel_launch(void* const* d_in, const int* in_sizes, int n_in,
                              void* d_out, int out_size) {
    const float* matrix = (const float*)d_in[0];
    const float* Wq = (const float*)d_in[1];
    const float* bq = (const float*)d_in[2];
    const float* Wk = (const float*)d_in[3];
    // d_in[4] = bk: mathematically eliminated (constant shift under softmax)
    const float* Wv = (const float*)d_in[5];
    const float* bv = (const float*)d_in[6];
    const float* Wo = (const float*)d_in[7];
    const float* bo = (const float*)d_in[8];
    const int* px = (const int*)d_in[9];
    const int* py = (const int*)d_in[10];

    cudaFuncSetAttribute(fused_local_attn,
                         cudaFuncAttributeMaxDynamicSharedMemorySize, SM_BYTES);
    fused_local_attn<<<NB, NT, SM_BYTES>>>(matrix, Wq, bq, Wk, Wv, bv, Wo, bo,
                                           px, py, (float*)d_out);
}

// round 10
// speedup vs baseline: 1.1603x; 1.1080x over previous
#include <cuda_runtime.h>
#include <cuda_bf16.h>

#define NB 64
#define NT 512
#define EMBED 1024
#define WIN 64
#define NK (2*WIN+1)   // 129
#define GW 256         // matrix W dimension
#define NPROD 32       // producer blocks in phase C
#define NKMAX 5        // max keys per producer (block 31 takes 5)

// Scratch (device globals: no allocation allowed)
__device__ float g_q[EMBED];
__device__ float g_wpart[2][EMBED];
__device__ float g_ypart[NPROD][EMBED];
__device__ float g_zpart[NPROD];
__device__ float g_o[EMBED];
// Grid barrier: EXACT style that passed 4/4 (atomic arrive + atomic poll + nanosleep).
__device__ unsigned g_arrive = 0;
__device__ unsigned g_rel = 0;

__device__ __forceinline__ void grid_sync() {
    __threadfence();
    __syncthreads();
    if (threadIdx.x == 0) {
        unsigned a = atomicAdd(&g_arrive, 1u) + 1u;
        unsigned target = (a + NB - 1u) / NB;
        if ((a % NB) == 0u) {
            atomicAdd(&g_rel, 1u);
        } else {
            while (atomicAdd(&g_rel, 0u) < target) { __nanosleep(32); }
        }
    }
    __syncthreads();
}

__device__ __forceinline__ float warp_reduce(float v) {
    #pragma unroll
    for (int o = 16; o; o >>= 1) v += __shfl_xor_sync(0xffffffffu, v, o);
    return v;
}

__device__ __forceinline__ float dot4(float4 a, float4 b) {
    return a.x * b.x + a.y * b.y + a.z * b.z + a.w * b.w;
}

// Static smem layout (floats):
//  [0,1024)     staging: x / abar / o (256 float4)
//  [1024,3072)  R1: 512 float4 (phase B), also q-stage (512 floats would fit here,
//               but q-stage uses [3072,3584) to avoid aliasing with R1)
//  [3072,3584)  sq: 512 floats (phase B q chunk)
//  [3584,3840)  R2: 64 float4
//  [3840,3968)  dotp: 16 warps x 8 slots
//  [3968,4000)  misc: warp accs / zinv / p_sh
#define SM_FLOATS 4000

__global__ void __launch_bounds__(NT, 1)
fused_local_attn(const float* __restrict__ matrix,
                 const float* __restrict__ Wq, const float* __restrict__ bq,
                 const float* __restrict__ Wk,
                 const float* __restrict__ Wv, const float* __restrict__ bv,
                 const float* __restrict__ Wo, const float* __restrict__ bo,
                 const int* __restrict__ ppx, const int* __restrict__ ppy,
                 float* __restrict__ out)
{
    const int tid  = threadIdx.x;
    const int bid  = blockIdx.x;
    const int wid  = tid >> 5;
    const int lane = tid & 31;

    __shared__ __align__(16) float sm[SM_FLOATS];
    float4* S0_4  = (float4*)sm;              // 256 float4 staging
    float4* R1_4  = (float4*)(sm + 1024);     // 512 float4
    float*  sq    = sm + 3072;                // 512 floats
    float4* R2_4  = (float4*)(sm + 3584);     // 64 float4
    float*  dotp  = sm + 3840;                // 16*8
    float*  misc  = sm + 3968;                // 32

    const int px = ppx[0], py = ppy[0];
    const float* rowbase = matrix + (size_t)(2 * px - WIN) * GW * EMBED;
    const float4* xvec4 = (const float4*)(rowbase + (size_t)(2 * py - WIN) * EMBED);
    const float4* keys4 = (const float4*)(rowbase + (size_t)(py - WIN) * EMBED);

    // =========== Phase A: q = Wq @ x + bq (16 rows/block, 1 warp/row) ====
    {
        if (tid < 256) S0_4[tid] = xvec4[tid];
        __syncthreads();
        int row = bid * 16 + wid;
        const float4* Wrow = (const float4*)(Wq + (size_t)row * EMBED);
        float acc = 0.f;
        #pragma unroll
        for (int i = 0; i < 8; i++)
            acc += dot4(Wrow[i * 32 + lane], S0_4[i * 32 + lane]);
        acc = warp_reduce(acc);
        if (lane == 0) misc[wid] = acc;
        __syncthreads();
        if (tid < 16) g_q[bid * 16 + tid] = misc[tid] + bq[bid * 16 + tid];
    }
    grid_sync();

    // ===== Phase B: w-partials. fc=bid>>5 (2 f-chunks of 512), et=bid&31 ==
    {
        const int fc = bid >> 5, et = bid & 31;
        const int f0 = fc * 512;
        if (tid < 128) ((float4*)sq)[tid] = __ldcg(&((const float4*)g_q)[f0 / 4 + tid]);
        __syncthreads();
        const int v = tid & 7, fl = tid >> 3;
        float4 acc = make_float4(0.f, 0.f, 0.f, 0.f);
        #pragma unroll
        for (int i = 0; i < 8; i++) {
            float qf = sq[i * 64 + fl];
            float4 wv = ((const float4*)Wk)[(size_t)(f0 + i * 64 + fl) * 256 + et * 8 + v];
            acc.x += qf * wv.x; acc.y += qf * wv.y; acc.z += qf * wv.z; acc.w += qf * wv.w;
        }
        R1_4[tid] = acc;
        __syncthreads();
        if (tid < 64) {                           // 512 -> 64
            int vv = tid & 7, g = tid >> 3;
            float4 s = make_float4(0.f, 0.f, 0.f, 0.f);
            #pragma unroll
            for (int j = 0; j < 8; j++) {
                float4 t4 = R1_4[vv + 8 * (g * 8 + j)];
                s.x += t4.x; s.y += t4.y; s.z += t4.z; s.w += t4.w;
            }
            R2_4[tid] = s;
        }
        __syncthreads();
        if (tid < 8) {                            // 64 -> 8 float4
            float4 s = make_float4(0.f, 0.f, 0.f, 0.f);
            #pragma unroll
            for (int g = 0; g < 8; g++) {
                float4 t4 = R2_4[tid + 8 * g];
                s.x += t4.x; s.y += t4.y; s.z += t4.z; s.w += t4.w;
            }
            ((float4*)g_wpart[fc])[et * 8 + tid] = s;
        }
    }
    grid_sync();

    // ===== Phase C (producers bid<NPROD): s_k, p_k=exp, y_part, z_part ===
    if (bid < NPROD) {
        const int kbase = bid * 4;
        const int nk = (bid == NPROD - 1) ? 5 : 4;   // block 31: k=124..128
        float4 w4 = make_float4(0.f, 0.f, 0.f, 0.f);
        float4 kv[NKMAX];
        #pragma unroll
        for (int j = 0; j < NKMAX; j++) kv[j] = make_float4(0.f, 0.f, 0.f, 0.f);
        if (tid < 256) {
            float4 a0 = __ldcg(&((const float4*)g_wpart[0])[tid]);
            float4 a1 = __ldcg(&((const float4*)g_wpart[1])[tid]);
            w4.x = a0.x + a1.x; w4.y = a0.y + a1.y;
            w4.z = a0.z + a1.z; w4.w = a0.w + a1.w;
            #pragma unroll
            for (int j = 0; j < NKMAX; j++)
                if (j < nk) kv[j] = keys4[(size_t)(kbase + j) * 256 + tid];
        }
        #pragma unroll
        for (int j = 0; j < NKMAX; j++) {
            float p = (j < nk) ? dot4(w4, kv[j]) : 0.f;
            p = warp_reduce(p);
            if (lane == 0) dotp[wid * 8 + j] = p;
        }
        __syncthreads();
        if (tid < NKMAX) {                        // thread j finalizes s_j -> p_j
            float s = 0.f;
            #pragma unroll
            for (int w = 0; w < 8; w++) s += dotp[w * 8 + tid];   // warps 0-7 hold t<256
            misc[20 + tid] = (tid < nk) ? __expf(s * 0.03125f) : 0.f;
        }
        __syncthreads();
        if (tid < 256) {
            float4 y = make_float4(0.f, 0.f, 0.f, 0.f);
            #pragma unroll
            for (int j = 0; j < NKMAX; j++) {
                float pk = misc[20 + j];
                y.x += pk * kv[j].x; y.y += pk * kv[j].y;
                y.z += pk * kv[j].z; y.w += pk * kv[j].w;
            }
            ((float4*)g_ypart[bid])[tid] = y;
        }
        if (tid == 0) {
            float z = 0.f;
            #pragma unroll
            for (int j = 0; j < NKMAX; j++) z += misc[20 + j];
            g_zpart[bid] = z;
        }
    }
    grid_sync();

    // ===== Phase E: reduce y/z -> abar, then o = Wv @ abar + bv ==========
    {
        if (wid == 0) {                            // z = sum of 32 zparts
            float z = __ldcg(&g_zpart[lane]);
            z = warp_reduce(z);
            if (lane == 0) misc[16] = 1.f / z;
        }
        float4 s0 = make_float4(0.f, 0.f, 0.f, 0.f);
        float4 s1 = make_float4(0.f, 0.f, 0.f, 0.f);
        if (tid < 256) {
            #pragma unroll
            for (int p = 0; p < NPROD; p += 2) {
                float4 a0 = __ldcg(&((const float4*)g_ypart[p])[tid]);
                float4 a1 = __ldcg(&((const float4*)g_ypart[p + 1])[tid]);
                s0.x += a0.x; s0.y += a0.y; s0.z += a0.z; s0.w += a0.w;
                s1.x += a1.x; s1.y += a1.y; s1.z += a1.z; s1.w += a1.w;
            }
        }
        __syncthreads();                           // zinv ready
        if (tid < 256) {
            float zinv = misc[16];
            float4 ab;
            ab.x = (s0.x + s1.x) * zinv; ab.y = (s0.y + s1.y) * zinv;
            ab.z = (s0.z + s1.z) * zinv; ab.w = (s0.w + s1.w) * zinv;
            S0_4[tid] = ab;
        }
        __syncthreads();
        int row = bid * 16 + wid;
        const float4* Wrow = (const float4*)(Wv + (size_t)row * EMBED);
        float acc = 0.f;
        #pragma unroll
        for (int i = 0; i < 8; i++)
            acc += dot4(Wrow[i * 32 + lane], S0_4[i * 32 + lane]);
        acc = warp_reduce(acc);
        if (lane == 0) misc[wid] = acc;
        __syncthreads();
        if (tid < 16) g_o[bid * 16 + tid] = misc[tid] + bv[bid * 16 + tid];
    }
    grid_sync();

    // =========== Phase F: out = Wo @ o + bo ==============================
    {
        if (tid < 256) S0_4[tid] = __ldcg(&((const float4*)g_o)[tid]);
        __syncthreads();
        int row = bid * 16 + wid;
        const float4* Wrow = (const float4*)(Wo + (size_t)row * EMBED);
        float acc = 0.f;
        #pragma unroll
        for (int i = 0; i < 8; i++)
            acc += dot4(Wrow[i * 32 + lane], S0_4[i * 32 + lane]);
        acc = warp_reduce(acc);
        if (lane == 0) misc[wid] = acc;
        __syncthreads();
        if (tid < 16) out[bid * 16 + tid] = misc[tid] + bo[bid * 16 + tid];
    }
}

extern "C" void kernel_launch(void* const* d_in, const int* in_sizes, int n_in,
                              void* d_out, int out_size) {
    const float* matrix = (const float*)d_in[0];
    const float* Wq = (const float*)d_in[1];
    const float* bq = (const float*)d_in[2];
    const float* Wk = (const float*)d_in[3];
    // d_in[4] = bk: eliminated (cancels in softmax ratio)
    const float* Wv = (const float*)d_in[5];
    const float* bv = (const float*)d_in[6];
    const float* Wo = (const float*)d_in[7];
    const float* bo = (const float*)d_in[8];
    const int* px = (const int*)d_in[9];
    const int* py = (const int*)d_in[10];

    fused_local_attn<<<NB, NT>>>(matrix, Wq, bq, Wk, Wv, bv, Wo, bo, px, py,
                                 (float*)d_out);
}